// round 2
// baseline (speedup 1.0000x reference)
#include <cuda_runtime.h>

#define NROWS 100000
#define CH 256
#define BM 64
#define BK 8
#define NTHR 256
#define MBLK ((NROWS + BM - 1) / BM)
#define S_SLICES 37
#define ROWS_PER 2704

// ---------------- scratch (static device globals; no allocation) ------------
__device__ float g_h [(size_t)NROWS * CH];
__device__ float g_h2[(size_t)NROWS * CH];
__device__ float g_q [(size_t)NROWS * CH];
__device__ float g_k [(size_t)NROWS * CH];
__device__ float g_v [(size_t)NROWS * CH];
__device__ float g_part[(size_t)S_SLICES * CH * CH];
__device__ float g_kvs[CH * CH];
__device__ float g_scal[CH + 4];   // [0]=||q||^2 [1]=||k||^2 [4..259]=col-sums of k

__device__ __forceinline__ float wred(float v) {
#pragma unroll
  for (int o = 16; o > 0; o >>= 1) v += __shfl_xor_sync(0xffffffffu, v, o);
  return v;
}

// ---------------------------------------------------------------------------
// C[r, j] = sum_k A[r,k] * W[j,k] + bias[j]   (NT gemm, K = CH = 256, BN = 256)
// warp w owns rows m0 + w*8 .. +7 ; lane l owns cols l*8 .. +7
// EPI: LNE -> LayerNorm(gamma,beta)+ReLU ; NORM -> atomicAdd(sum C^2) ;
//      COLSUM -> atomicAdd per-column sums
// ---------------------------------------------------------------------------
template<bool LNE, bool NORM, bool COLSUM>
__global__ void __launch_bounds__(NTHR) gemm_nt(
    const float* __restrict__ A, const float* __restrict__ W,
    const float* __restrict__ bias, float* __restrict__ C,
    const float* __restrict__ gamma, const float* __restrict__ beta,
    float* __restrict__ normAcc, float* __restrict__ colAcc)
{
  __shared__ float As[BK][BM + 1];
  __shared__ float Bs[BK][CH];
  __shared__ float sCol[CH];
  __shared__ float sRed[8];

  const int tid = threadIdx.x, w = tid >> 5, l = tid & 31;
  const int m0 = blockIdx.x * BM;

  if (COLSUM && tid < CH) sCol[tid] = 0.f;

  const int arow = tid >> 2;
  const int akk  = (tid & 3) * 2;
  const bool aval = (m0 + arow) < NROWS;
  const float* Aptr = A + (size_t)(m0 + arow) * CH + akk;
  const float* Wptr = W + (size_t)tid * CH;

  float acc[8][8];
#pragma unroll
  for (int i = 0; i < 8; i++)
#pragma unroll
    for (int j = 0; j < 8; j++) acc[i][j] = 0.f;

  float2 aR = aval ? *(const float2*)Aptr : make_float2(0.f, 0.f);
  float4 bR0 = *(const float4*)(Wptr);
  float4 bR1 = *(const float4*)(Wptr + 4);

  for (int k0 = 0; k0 < CH; k0 += BK) {
    __syncthreads();
    As[akk][arow]     = aR.x;
    As[akk + 1][arow] = aR.y;
    Bs[0][tid] = bR0.x; Bs[1][tid] = bR0.y; Bs[2][tid] = bR0.z; Bs[3][tid] = bR0.w;
    Bs[4][tid] = bR1.x; Bs[5][tid] = bR1.y; Bs[6][tid] = bR1.z; Bs[7][tid] = bR1.w;
    __syncthreads();
    if (k0 + BK < CH) {
      aR  = aval ? *(const float2*)(Aptr + k0 + BK) : make_float2(0.f, 0.f);
      bR0 = *(const float4*)(Wptr + k0 + BK);
      bR1 = *(const float4*)(Wptr + k0 + BK + 4);
    }
#pragma unroll
    for (int kk = 0; kk < BK; kk++) {
      float a[8], b[8];
#pragma unroll
      for (int i = 0; i < 8; i++) a[i] = As[kk][w * 8 + i];
      float4 b0 = *(const float4*)&Bs[kk][l * 8];
      float4 b1 = *(const float4*)&Bs[kk][l * 8 + 4];
      b[0]=b0.x; b[1]=b0.y; b[2]=b0.z; b[3]=b0.w;
      b[4]=b1.x; b[5]=b1.y; b[6]=b1.z; b[7]=b1.w;
#pragma unroll
      for (int i = 0; i < 8; i++)
#pragma unroll
        for (int j = 0; j < 8; j++)
          acc[i][j] = fmaf(a[i], b[j], acc[i][j]);
    }
  }

  // ---------------- epilogue ----------------
  float bf[8];
  { float4 t0 = *(const float4*)&bias[l*8]; float4 t1 = *(const float4*)&bias[l*8+4];
    bf[0]=t0.x; bf[1]=t0.y; bf[2]=t0.z; bf[3]=t0.w;
    bf[4]=t1.x; bf[5]=t1.y; bf[6]=t1.z; bf[7]=t1.w; }
  float gf[8], btf[8];
  if (LNE) {
    float4 t0 = *(const float4*)&gamma[l*8]; float4 t1 = *(const float4*)&gamma[l*8+4];
    gf[0]=t0.x; gf[1]=t0.y; gf[2]=t0.z; gf[3]=t0.w;
    gf[4]=t1.x; gf[5]=t1.y; gf[6]=t1.z; gf[7]=t1.w;
    float4 u0 = *(const float4*)&beta[l*8];  float4 u1 = *(const float4*)&beta[l*8+4];
    btf[0]=u0.x; btf[1]=u0.y; btf[2]=u0.z; btf[3]=u0.w;
    btf[4]=u1.x; btf[5]=u1.y; btf[6]=u1.z; btf[7]=u1.w;
  }

  float nrm = 0.f;
  float colp[8];
#pragma unroll
  for (int j = 0; j < 8; j++) colp[j] = 0.f;

#pragma unroll
  for (int i = 0; i < 8; i++) {
    const int r = m0 + w * 8 + i;
    const bool valid = r < NROWS;
#pragma unroll
    for (int j = 0; j < 8; j++) acc[i][j] += bf[j];
    if (NORM && valid) {
#pragma unroll
      for (int j = 0; j < 8; j++) nrm = fmaf(acc[i][j], acc[i][j], nrm);
    }
    if (COLSUM && valid) {
#pragma unroll
      for (int j = 0; j < 8; j++) colp[j] += acc[i][j];
    }
    if (LNE) {
      float s1 = 0.f, s2 = 0.f;
#pragma unroll
      for (int j = 0; j < 8; j++) { s1 += acc[i][j]; s2 = fmaf(acc[i][j], acc[i][j], s2); }
      s1 = wred(s1); s2 = wred(s2);
      const float mu = s1 * (1.f / CH);
      const float rs = rsqrtf(s2 * (1.f / CH) - mu * mu + 1e-5f);
#pragma unroll
      for (int j = 0; j < 8; j++) {
        float vv = (acc[i][j] - mu) * rs * gf[j] + btf[j];
        acc[i][j] = fmaxf(vv, 0.f);
      }
    }
    if (valid) {
      float4 o0 = make_float4(acc[i][0], acc[i][1], acc[i][2], acc[i][3]);
      float4 o1 = make_float4(acc[i][4], acc[i][5], acc[i][6], acc[i][7]);
      *(float4*)&C[(size_t)r * CH + l * 8]     = o0;
      *(float4*)&C[(size_t)r * CH + l * 8 + 4] = o1;
    }
  }

  if (NORM) {
    float p = wred(nrm);
    if (l == 0) sRed[w] = p;
    __syncthreads();
    if (tid == 0) {
      float s = 0.f;
#pragma unroll
      for (int i = 0; i < 8; i++) s += sRed[i];
      atomicAdd(normAcc, s);
    }
  }
  if (COLSUM) {
#pragma unroll
    for (int j = 0; j < 8; j++) atomicAdd(&sCol[l * 8 + j], colp[j]);
    __syncthreads();
    if (tid < CH) atomicAdd(&colAcc[tid], sCol[tid]);
  }
}

// ---------------------------------------------------------------------------
// part[s][m][d] = sum over rows n in slice s of K[n,m] * V[n,d]
// ---------------------------------------------------------------------------
__global__ void __launch_bounds__(NTHR) kvs_kernel(
    const float* __restrict__ K, const float* __restrict__ V,
    float* __restrict__ part)
{
  __shared__ float As[BK][BM + 1];
  __shared__ float Bs[BK][CH];

  const int tid = threadIdx.x, w = tid >> 5, l = tid & 31;
  const int m0 = blockIdx.x * BM;
  const int n0 = blockIdx.y * ROWS_PER;

  const int akk = tid >> 5;            // 0..7
  const int am  = (tid & 31) * 2;      // 0..62
  const int bkk = tid >> 5;
  const int bc  = (tid & 31) * 8;

  float acc[8][8];
#pragma unroll
  for (int i = 0; i < 8; i++)
#pragma unroll
    for (int j = 0; j < 8; j++) acc[i][j] = 0.f;

  float2 aR; float4 bR0, bR1;
  {
    int n = n0 + akk;
    aR  = (n < NROWS) ? *(const float2*)&K[(size_t)n * CH + m0 + am] : make_float2(0.f, 0.f);
    if (n < NROWS) { bR0 = *(const float4*)&V[(size_t)n * CH + bc];
                     bR1 = *(const float4*)&V[(size_t)n * CH + bc + 4]; }
    else { bR0 = make_float4(0,0,0,0); bR1 = make_float4(0,0,0,0); }
  }

  for (int k0 = 0; k0 < ROWS_PER; k0 += BK) {
    __syncthreads();
    As[akk][am]     = aR.x;
    As[akk][am + 1] = aR.y;
    *(float4*)&Bs[bkk][bc]     = bR0;
    *(float4*)&Bs[bkk][bc + 4] = bR1;
    __syncthreads();
    if (k0 + BK < ROWS_PER) {
      int n = n0 + k0 + BK + akk;
      aR = (n < NROWS) ? *(const float2*)&K[(size_t)n * CH + m0 + am] : make_float2(0.f, 0.f);
      int nb = n0 + k0 + BK + bkk;
      if (nb < NROWS) { bR0 = *(const float4*)&V[(size_t)nb * CH + bc];
                        bR1 = *(const float4*)&V[(size_t)nb * CH + bc + 4]; }
      else { bR0 = make_float4(0,0,0,0); bR1 = make_float4(0,0,0,0); }
    }
#pragma unroll
    for (int kk = 0; kk < BK; kk++) {
      float a[8], b[8];
#pragma unroll
      for (int i = 0; i < 8; i++) a[i] = As[kk][w * 8 + i];
      float4 b0 = *(const float4*)&Bs[kk][l * 8];
      float4 b1 = *(const float4*)&Bs[kk][l * 8 + 4];
      b[0]=b0.x; b[1]=b0.y; b[2]=b0.z; b[3]=b0.w;
      b[4]=b1.x; b[5]=b1.y; b[6]=b1.z; b[7]=b1.w;
#pragma unroll
      for (int i = 0; i < 8; i++)
#pragma unroll
        for (int j = 0; j < 8; j++)
          acc[i][j] = fmaf(a[i], b[j], acc[i][j]);
    }
  }

  float* dst = part + (size_t)blockIdx.y * CH * CH;
#pragma unroll
  for (int i = 0; i < 8; i++) {
    int m = m0 + w * 8 + i;
    float4 o0 = make_float4(acc[i][0], acc[i][1], acc[i][2], acc[i][3]);
    float4 o1 = make_float4(acc[i][4], acc[i][5], acc[i][6], acc[i][7]);
    *(float4*)&dst[(size_t)m * CH + l * 8]     = o0;
    *(float4*)&dst[(size_t)m * CH + l * 8 + 4] = o1;
  }
}

__global__ void kvs_reduce(const float* __restrict__ part, float* __restrict__ kvs) {
  int idx = blockIdx.x * blockDim.x + threadIdx.x;
  if (idx < CH * CH) {
    float s = 0.f;
#pragma unroll
    for (int ss = 0; ss < S_SLICES; ss++) s += part[(size_t)ss * CH * CH + idx];
    kvs[idx] = s;
  }
}

__global__ void zero_kernel(float* p, int n) {
  int i = blockIdx.x * blockDim.x + threadIdx.x;
  if (i < n) p[i] = 0.f;
}

// ---------------------------------------------------------------------------
// out = ReLU(LN(0.5*attn + 0.5*prev)),
// attn = (c * (Q@KVS) + n*V) / (c * (Q . ks_sum) + n),  c = rsqrt(||q||^2 ||k||^2)
// ---------------------------------------------------------------------------
__global__ void __launch_bounds__(NTHR) attn_kernel(
    const float* __restrict__ Q, const float* __restrict__ KVS,
    const float* __restrict__ V, const float* __restrict__ P,
    const float* __restrict__ scal,
    const float* __restrict__ gamma, const float* __restrict__ beta,
    float* __restrict__ Cout)
{
  __shared__ float As[BK][BM + 1];
  __shared__ float Bs[BK][CH];

  const int tid = threadIdx.x, w = tid >> 5, l = tid & 31;
  const int m0 = blockIdx.x * BM;

  const int arow = tid >> 2;
  const int akk  = (tid & 3) * 2;
  const bool aval = (m0 + arow) < NROWS;
  const float* Aptr = Q + (size_t)(m0 + arow) * CH + akk;
  const int bkk = tid >> 5;
  const int bc  = (tid & 31) * 8;

  float acc[8][8];
#pragma unroll
  for (int i = 0; i < 8; i++)
#pragma unroll
    for (int j = 0; j < 8; j++) acc[i][j] = 0.f;

  float2 aR = aval ? *(const float2*)Aptr : make_float2(0.f, 0.f);
  float4 bR0 = *(const float4*)&KVS[(size_t)bkk * CH + bc];
  float4 bR1 = *(const float4*)&KVS[(size_t)bkk * CH + bc + 4];

  for (int k0 = 0; k0 < CH; k0 += BK) {
    __syncthreads();
    As[akk][arow]     = aR.x;
    As[akk + 1][arow] = aR.y;
    *(float4*)&Bs[bkk][bc]     = bR0;
    *(float4*)&Bs[bkk][bc + 4] = bR1;
    __syncthreads();
    if (k0 + BK < CH) {
      aR  = aval ? *(const float2*)(Aptr + k0 + BK) : make_float2(0.f, 0.f);
      bR0 = *(const float4*)&KVS[(size_t)(k0 + BK + bkk) * CH + bc];
      bR1 = *(const float4*)&KVS[(size_t)(k0 + BK + bkk) * CH + bc + 4];
    }
#pragma unroll
    for (int kk = 0; kk < BK; kk++) {
      float a[8], b[8];
#pragma unroll
      for (int i = 0; i < 8; i++) a[i] = As[kk][w * 8 + i];
      float4 b0 = *(const float4*)&Bs[kk][l * 8];
      float4 b1 = *(const float4*)&Bs[kk][l * 8 + 4];
      b[0]=b0.x; b[1]=b0.y; b[2]=b0.z; b[3]=b0.w;
      b[4]=b1.x; b[5]=b1.y; b[6]=b1.z; b[7]=b1.w;
#pragma unroll
      for (int i = 0; i < 8; i++)
#pragma unroll
        for (int j = 0; j < 8; j++)
          acc[i][j] = fmaf(a[i], b[j], acc[i][j]);
    }
  }

  // ---------------- epilogue ----------------
  const float cN = rsqrtf(scal[0] * scal[1]);
  const float nF = (float)NROWS;
  float ks[8];
#pragma unroll
  for (int j = 0; j < 8; j++) ks[j] = scal[4 + l * 8 + j];
  float gf[8], btf[8];
  {
    float4 t0 = *(const float4*)&gamma[l*8]; float4 t1 = *(const float4*)&gamma[l*8+4];
    gf[0]=t0.x; gf[1]=t0.y; gf[2]=t0.z; gf[3]=t0.w;
    gf[4]=t1.x; gf[5]=t1.y; gf[6]=t1.z; gf[7]=t1.w;
    float4 u0 = *(const float4*)&beta[l*8];  float4 u1 = *(const float4*)&beta[l*8+4];
    btf[0]=u0.x; btf[1]=u0.y; btf[2]=u0.z; btf[3]=u0.w;
    btf[4]=u1.x; btf[5]=u1.y; btf[6]=u1.z; btf[7]=u1.w;
  }

#pragma unroll
  for (int i = 0; i < 8; i++) {
    const int r = m0 + w * 8 + i;
    const bool valid = r < NROWS;
    float q8[8], v8[8], p8[8];
    if (valid) {
      float4 t0 = *(const float4*)&Q[(size_t)r * CH + l * 8];
      float4 t1 = *(const float4*)&Q[(size_t)r * CH + l * 8 + 4];
      q8[0]=t0.x; q8[1]=t0.y; q8[2]=t0.z; q8[3]=t0.w;
      q8[4]=t1.x; q8[5]=t1.y; q8[6]=t1.z; q8[7]=t1.w;
      float4 v0 = *(const float4*)&V[(size_t)r * CH + l * 8];
      float4 v1 = *(const float4*)&V[(size_t)r * CH + l * 8 + 4];
      v8[0]=v0.x; v8[1]=v0.y; v8[2]=v0.z; v8[3]=v0.w;
      v8[4]=v1.x; v8[5]=v1.y; v8[6]=v1.z; v8[7]=v1.w;
      float4 p0 = *(const float4*)&P[(size_t)r * CH + l * 8];
      float4 p1 = *(const float4*)&P[(size_t)r * CH + l * 8 + 4];
      p8[0]=p0.x; p8[1]=p0.y; p8[2]=p0.z; p8[3]=p0.w;
      p8[4]=p1.x; p8[5]=p1.y; p8[6]=p1.z; p8[7]=p1.w;
    } else {
#pragma unroll
      for (int j = 0; j < 8; j++) { q8[j]=0.f; v8[j]=0.f; p8[j]=0.f; }
    }
    float dp = 0.f;
#pragma unroll
    for (int j = 0; j < 8; j++) dp = fmaf(q8[j], ks[j], dp);
    dp = wred(dp);
    const float denom = fmaf(cN, dp, nF);
    const float inv = 1.f / denom;

    float hm[8];
#pragma unroll
    for (int j = 0; j < 8; j++) {
      float attn = (fmaf(cN, acc[i][j], nF * v8[j])) * inv;
      hm[j] = 0.5f * (attn + p8[j]);
    }
    float s1 = 0.f, s2 = 0.f;
#pragma unroll
    for (int j = 0; j < 8; j++) { s1 += hm[j]; s2 = fmaf(hm[j], hm[j], s2); }
    s1 = wred(s1); s2 = wred(s2);
    const float mu = s1 * (1.f / CH);
    const float rs = rsqrtf(s2 * (1.f / CH) - mu * mu + 1e-5f);
    if (valid) {
      float o[8];
#pragma unroll
      for (int j = 0; j < 8; j++)
        o[j] = fmaxf((hm[j] - mu) * rs * gf[j] + btf[j], 0.f);
      float4 o0 = make_float4(o[0], o[1], o[2], o[3]);
      float4 o1 = make_float4(o[4], o[5], o[6], o[7]);
      *(float4*)&Cout[(size_t)r * CH + l * 8]     = o0;
      *(float4*)&Cout[(size_t)r * CH + l * 8 + 4] = o1;
    }
  }
}

// ---------------------------------------------------------------------------
extern "C" void kernel_launch(void* const* d_in, const int* in_sizes, int n_in,
                              void* d_out, int out_size) {
  (void)in_sizes; (void)n_in; (void)out_size;
  const float* x    = (const float*)d_in[0];
  const float* fc_w = (const float*)d_in[1];
  const float* fc_b = (const float*)d_in[2];
  const float* Wq_w = (const float*)d_in[3];
  const float* Wq_b = (const float*)d_in[4];
  const float* Wk_w = (const float*)d_in[5];
  const float* Wk_b = (const float*)d_in[6];
  const float* Wv_w = (const float*)d_in[7];
  const float* Wv_b = (const float*)d_in[8];
  const float* ln_g = (const float*)d_in[9];
  const float* ln_b = (const float*)d_in[10];
  float* out = (float*)d_out;

  float *hA, *hB, *q, *k, *v, *part, *kvs, *scal;
  cudaGetSymbolAddress((void**)&hA,   g_h);
  cudaGetSymbolAddress((void**)&hB,   g_h2);
  cudaGetSymbolAddress((void**)&q,    g_q);
  cudaGetSymbolAddress((void**)&k,    g_k);
  cudaGetSymbolAddress((void**)&v,    g_v);
  cudaGetSymbolAddress((void**)&part, g_part);
  cudaGetSymbolAddress((void**)&kvs,  g_kvs);
  cudaGetSymbolAddress((void**)&scal, g_scal);

  // h0 = relu(LN(x @ fc_w^T + fc_b))
  gemm_nt<true, false, false><<<MBLK, NTHR>>>(
      x, fc_w, fc_b, hA, ln_g, ln_b, nullptr, nullptr);

  for (int L = 0; L < 2; L++) {
    const float* h = L ? hB : hA;
    float* ob = L ? out : hB;
    const size_t wo = (size_t)L * CH * CH;
    const size_t bo = (size_t)L * CH;

    zero_kernel<<<1, CH + 4>>>(scal, CH + 4);
    gemm_nt<false, true, false><<<MBLK, NTHR>>>(
        h, Wq_w + wo, Wq_b + bo, q, nullptr, nullptr, scal + 0, nullptr);
    gemm_nt<false, true, true><<<MBLK, NTHR>>>(
        h, Wk_w + wo, Wk_b + bo, k, nullptr, nullptr, scal + 1, scal + 4);
    gemm_nt<false, false, false><<<MBLK, NTHR>>>(
        h, Wv_w + wo, Wv_b + bo, v, nullptr, nullptr, nullptr, nullptr);
    kvs_kernel<<<dim3(CH / BM, S_SLICES), NTHR>>>(k, v, part);
    kvs_reduce<<<64, 1024>>>(part, kvs);
    attn_kernel<<<MBLK, NTHR>>>(
        q, kvs, v, h, scal, ln_g + (size_t)(L + 1) * CH, ln_b + (size_t)(L + 1) * CH, ob);
  }
}

// round 3
// speedup vs baseline: 1.0015x; 1.0015x over previous
#include <cuda_runtime.h>

#define NROWS 100000
#define CH 256
#define BM 64
#define BK 8
#define NTHR 256
#define MBLK ((NROWS + BM - 1) / BM)
#define S_SLICES 37
#define ROWS_PER 2704

// ---------------- scratch (static device globals; no allocation) ------------
__device__ float g_h [(size_t)NROWS * CH];
__device__ float g_h2[(size_t)NROWS * CH];
__device__ float g_q [(size_t)NROWS * CH];
__device__ float g_k [(size_t)NROWS * CH];
__device__ float g_v [(size_t)NROWS * CH];
__device__ float g_part[(size_t)S_SLICES * CH * CH];
__device__ float g_kvs[CH * CH];
__device__ float g_scal[CH + 4];   // [0]=||q||^2 [1]=||k||^2 [4..259]=col-sums of k

__device__ __forceinline__ float wred(float v) {
#pragma unroll
  for (int o = 16; o > 0; o >>= 1) v += __shfl_xor_sync(0xffffffffu, v, o);
  return v;
}

// ---------------------------------------------------------------------------
// C[r, j] = sum_k A[r,k] * W[j,k] + bias[j]   (NT gemm, K = CH = 256, BN = 256)
// warp w owns rows m0 + w*8 .. +7 ; lane l owns cols l*8 .. +7
// EPI: LNE -> LayerNorm(gamma,beta)+ReLU ; NORM -> atomicAdd(sum C^2) ;
//      COLSUM -> atomicAdd per-column sums
// ---------------------------------------------------------------------------
template<bool LNE, bool NORM, bool COLSUM>
__global__ void __launch_bounds__(NTHR) gemm_nt(
    const float* __restrict__ A, const float* __restrict__ W,
    const float* __restrict__ bias, float* __restrict__ C,
    const float* __restrict__ gamma, const float* __restrict__ beta,
    float* __restrict__ normAcc, float* __restrict__ colAcc)
{
  __shared__ float As[BK][BM + 1];
  __shared__ float Bs[BK][CH];
  __shared__ float sCol[CH];
  __shared__ float sRed[8];

  const int tid = threadIdx.x, w = tid >> 5, l = tid & 31;
  const int m0 = blockIdx.x * BM;

  if (COLSUM && tid < CH) sCol[tid] = 0.f;

  const int arow = tid >> 2;
  const int akk  = (tid & 3) * 2;
  const bool aval = (m0 + arow) < NROWS;
  const float* Aptr = A + (size_t)(m0 + arow) * CH + akk;
  const float* Wptr = W + (size_t)tid * CH;

  float acc[8][8];
#pragma unroll
  for (int i = 0; i < 8; i++)
#pragma unroll
    for (int j = 0; j < 8; j++) acc[i][j] = 0.f;

  float2 aR = aval ? *(const float2*)Aptr : make_float2(0.f, 0.f);
  float4 bR0 = *(const float4*)(Wptr);
  float4 bR1 = *(const float4*)(Wptr + 4);

  for (int k0 = 0; k0 < CH; k0 += BK) {
    __syncthreads();
    As[akk][arow]     = aR.x;
    As[akk + 1][arow] = aR.y;
    Bs[0][tid] = bR0.x; Bs[1][tid] = bR0.y; Bs[2][tid] = bR0.z; Bs[3][tid] = bR0.w;
    Bs[4][tid] = bR1.x; Bs[5][tid] = bR1.y; Bs[6][tid] = bR1.z; Bs[7][tid] = bR1.w;
    __syncthreads();
    if (k0 + BK < CH) {
      aR  = aval ? *(const float2*)(Aptr + k0 + BK) : make_float2(0.f, 0.f);
      bR0 = *(const float4*)(Wptr + k0 + BK);
      bR1 = *(const float4*)(Wptr + k0 + BK + 4);
    }
#pragma unroll
    for (int kk = 0; kk < BK; kk++) {
      float a[8], b[8];
#pragma unroll
      for (int i = 0; i < 8; i++) a[i] = As[kk][w * 8 + i];
      float4 b0 = *(const float4*)&Bs[kk][l * 8];
      float4 b1 = *(const float4*)&Bs[kk][l * 8 + 4];
      b[0]=b0.x; b[1]=b0.y; b[2]=b0.z; b[3]=b0.w;
      b[4]=b1.x; b[5]=b1.y; b[6]=b1.z; b[7]=b1.w;
#pragma unroll
      for (int i = 0; i < 8; i++)
#pragma unroll
        for (int j = 0; j < 8; j++)
          acc[i][j] = fmaf(a[i], b[j], acc[i][j]);
    }
  }

  // ---------------- epilogue ----------------
  float bf[8];
  { float4 t0 = *(const float4*)&bias[l*8]; float4 t1 = *(const float4*)&bias[l*8+4];
    bf[0]=t0.x; bf[1]=t0.y; bf[2]=t0.z; bf[3]=t0.w;
    bf[4]=t1.x; bf[5]=t1.y; bf[6]=t1.z; bf[7]=t1.w; }
  float gf[8], btf[8];
  if (LNE) {
    float4 t0 = *(const float4*)&gamma[l*8]; float4 t1 = *(const float4*)&gamma[l*8+4];
    gf[0]=t0.x; gf[1]=t0.y; gf[2]=t0.z; gf[3]=t0.w;
    gf[4]=t1.x; gf[5]=t1.y; gf[6]=t1.z; gf[7]=t1.w;
    float4 u0 = *(const float4*)&beta[l*8];  float4 u1 = *(const float4*)&beta[l*8+4];
    btf[0]=u0.x; btf[1]=u0.y; btf[2]=u0.z; btf[3]=u0.w;
    btf[4]=u1.x; btf[5]=u1.y; btf[6]=u1.z; btf[7]=u1.w;
  }

  float nrm = 0.f;
  float colp[8];
#pragma unroll
  for (int j = 0; j < 8; j++) colp[j] = 0.f;

#pragma unroll
  for (int i = 0; i < 8; i++) {
    const int r = m0 + w * 8 + i;
    const bool valid = r < NROWS;
#pragma unroll
    for (int j = 0; j < 8; j++) acc[i][j] += bf[j];
    if (NORM && valid) {
#pragma unroll
      for (int j = 0; j < 8; j++) nrm = fmaf(acc[i][j], acc[i][j], nrm);
    }
    if (COLSUM && valid) {
#pragma unroll
      for (int j = 0; j < 8; j++) colp[j] += acc[i][j];
    }
    if (LNE) {
      float s1 = 0.f, s2 = 0.f;
#pragma unroll
      for (int j = 0; j < 8; j++) { s1 += acc[i][j]; s2 = fmaf(acc[i][j], acc[i][j], s2); }
      s1 = wred(s1); s2 = wred(s2);
      const float mu = s1 * (1.f / CH);
      const float rs = rsqrtf(s2 * (1.f / CH) - mu * mu + 1e-5f);
#pragma unroll
      for (int j = 0; j < 8; j++) {
        float vv = (acc[i][j] - mu) * rs * gf[j] + btf[j];
        acc[i][j] = fmaxf(vv, 0.f);
      }
    }
    if (valid) {
      float4 o0 = make_float4(acc[i][0], acc[i][1], acc[i][2], acc[i][3]);
      float4 o1 = make_float4(acc[i][4], acc[i][5], acc[i][6], acc[i][7]);
      *(float4*)&C[(size_t)r * CH + l * 8]     = o0;
      *(float4*)&C[(size_t)r * CH + l * 8 + 4] = o1;
    }
  }

  if (NORM) {
    float p = wred(nrm);
    if (l == 0) sRed[w] = p;
    __syncthreads();
    if (tid == 0) {
      float s = 0.f;
#pragma unroll
      for (int i = 0; i < 8; i++) s += sRed[i];
      atomicAdd(normAcc, s);
    }
  }
  if (COLSUM) {
#pragma unroll
    for (int j = 0; j < 8; j++) atomicAdd(&sCol[l * 8 + j], colp[j]);
    __syncthreads();
    if (tid < CH) atomicAdd(&colAcc[tid], sCol[tid]);
  }
}

// ---------------------------------------------------------------------------
// part[s][m][d] = sum over rows n in slice s of K[n,m] * V[n,d]
// ---------------------------------------------------------------------------
__global__ void __launch_bounds__(NTHR) kvs_kernel(
    const float* __restrict__ K, const float* __restrict__ V,
    float* __restrict__ part)
{
  __shared__ float As[BK][BM + 1];
  __shared__ float Bs[BK][CH];

  const int tid = threadIdx.x, w = tid >> 5, l = tid & 31;
  const int m0 = blockIdx.x * BM;
  const int n0 = blockIdx.y * ROWS_PER;

  const int akk = tid >> 5;            // 0..7
  const int am  = (tid & 31) * 2;      // 0..62
  const int bkk = tid >> 5;
  const int bc  = (tid & 31) * 8;

  float acc[8][8];
#pragma unroll
  for (int i = 0; i < 8; i++)
#pragma unroll
    for (int j = 0; j < 8; j++) acc[i][j] = 0.f;

  float2 aR; float4 bR0, bR1;
  {
    int n = n0 + akk;
    aR  = (n < NROWS) ? *(const float2*)&K[(size_t)n * CH + m0 + am] : make_float2(0.f, 0.f);
    if (n < NROWS) { bR0 = *(const float4*)&V[(size_t)n * CH + bc];
                     bR1 = *(const float4*)&V[(size_t)n * CH + bc + 4]; }
    else { bR0 = make_float4(0,0,0,0); bR1 = make_float4(0,0,0,0); }
  }

  for (int k0 = 0; k0 < ROWS_PER; k0 += BK) {
    __syncthreads();
    As[akk][am]     = aR.x;
    As[akk][am + 1] = aR.y;
    *(float4*)&Bs[bkk][bc]     = bR0;
    *(float4*)&Bs[bkk][bc + 4] = bR1;
    __syncthreads();
    if (k0 + BK < ROWS_PER) {
      int n = n0 + k0 + BK + akk;
      aR = (n < NROWS) ? *(const float2*)&K[(size_t)n * CH + m0 + am] : make_float2(0.f, 0.f);
      int nb = n0 + k0 + BK + bkk;
      if (nb < NROWS) { bR0 = *(const float4*)&V[(size_t)nb * CH + bc];
                        bR1 = *(const float4*)&V[(size_t)nb * CH + bc + 4]; }
      else { bR0 = make_float4(0,0,0,0); bR1 = make_float4(0,0,0,0); }
    }
#pragma unroll
    for (int kk = 0; kk < BK; kk++) {
      float a[8], b[8];
#pragma unroll
      for (int i = 0; i < 8; i++) a[i] = As[kk][w * 8 + i];
      float4 b0 = *(const float4*)&Bs[kk][l * 8];
      float4 b1 = *(const float4*)&Bs[kk][l * 8 + 4];
      b[0]=b0.x; b[1]=b0.y; b[2]=b0.z; b[3]=b0.w;
      b[4]=b1.x; b[5]=b1.y; b[6]=b1.z; b[7]=b1.w;
#pragma unroll
      for (int i = 0; i < 8; i++)
#pragma unroll
        for (int j = 0; j < 8; j++)
          acc[i][j] = fmaf(a[i], b[j], acc[i][j]);
    }
  }

  float* dst = part + (size_t)blockIdx.y * CH * CH;
#pragma unroll
  for (int i = 0; i < 8; i++) {
    int m = m0 + w * 8 + i;
    float4 o0 = make_float4(acc[i][0], acc[i][1], acc[i][2], acc[i][3]);
    float4 o1 = make_float4(acc[i][4], acc[i][5], acc[i][6], acc[i][7]);
    *(float4*)&dst[(size_t)m * CH + l * 8]     = o0;
    *(float4*)&dst[(size_t)m * CH + l * 8 + 4] = o1;
  }
}

__global__ void kvs_reduce(const float* __restrict__ part, float* __restrict__ kvs) {
  int idx = blockIdx.x * blockDim.x + threadIdx.x;
  if (idx < CH * CH) {
    float s = 0.f;
#pragma unroll
    for (int ss = 0; ss < S_SLICES; ss++) s += part[(size_t)ss * CH * CH + idx];
    kvs[idx] = s;
  }
}

__global__ void zero_kernel(float* p, int n) {
  int i = blockIdx.x * blockDim.x + threadIdx.x;
  if (i < n) p[i] = 0.f;
}

// ---------------------------------------------------------------------------
// out = ReLU(LN(0.5*attn + 0.5*prev)),
// attn = (c * (Q@KVS) + n*V) / (c * (Q . ks_sum) + n),  c = rsqrt(||q||^2 ||k||^2)
// ---------------------------------------------------------------------------
__global__ void __launch_bounds__(NTHR) attn_kernel(
    const float* __restrict__ Q, const float* __restrict__ KVS,
    const float* __restrict__ V, const float* __restrict__ P,
    const float* __restrict__ scal,
    const float* __restrict__ gamma, const float* __restrict__ beta,
    float* __restrict__ Cout)
{
  __shared__ float As[BK][BM + 1];
  __shared__ float Bs[BK][CH];

  const int tid = threadIdx.x, w = tid >> 5, l = tid & 31;
  const int m0 = blockIdx.x * BM;

  const int arow = tid >> 2;
  const int akk  = (tid & 3) * 2;
  const bool aval = (m0 + arow) < NROWS;
  const float* Aptr = Q + (size_t)(m0 + arow) * CH + akk;
  const int bkk = tid >> 5;
  const int bc  = (tid & 31) * 8;

  float acc[8][8];
#pragma unroll
  for (int i = 0; i < 8; i++)
#pragma unroll
    for (int j = 0; j < 8; j++) acc[i][j] = 0.f;

  float2 aR = aval ? *(const float2*)Aptr : make_float2(0.f, 0.f);
  float4 bR0 = *(const float4*)&KVS[(size_t)bkk * CH + bc];
  float4 bR1 = *(const float4*)&KVS[(size_t)bkk * CH + bc + 4];

  for (int k0 = 0; k0 < CH; k0 += BK) {
    __syncthreads();
    As[akk][arow]     = aR.x;
    As[akk + 1][arow] = aR.y;
    *(float4*)&Bs[bkk][bc]     = bR0;
    *(float4*)&Bs[bkk][bc + 4] = bR1;
    __syncthreads();
    if (k0 + BK < CH) {
      aR  = aval ? *(const float2*)(Aptr + k0 + BK) : make_float2(0.f, 0.f);
      bR0 = *(const float4*)&KVS[(size_t)(k0 + BK + bkk) * CH + bc];
      bR1 = *(const float4*)&KVS[(size_t)(k0 + BK + bkk) * CH + bc + 4];
    }
#pragma unroll
    for (int kk = 0; kk < BK; kk++) {
      float a[8], b[8];
#pragma unroll
      for (int i = 0; i < 8; i++) a[i] = As[kk][w * 8 + i];
      float4 b0 = *(const float4*)&Bs[kk][l * 8];
      float4 b1 = *(const float4*)&Bs[kk][l * 8 + 4];
      b[0]=b0.x; b[1]=b0.y; b[2]=b0.z; b[3]=b0.w;
      b[4]=b1.x; b[5]=b1.y; b[6]=b1.z; b[7]=b1.w;
#pragma unroll
      for (int i = 0; i < 8; i++)
#pragma unroll
        for (int j = 0; j < 8; j++)
          acc[i][j] = fmaf(a[i], b[j], acc[i][j]);
    }
  }

  // ---------------- epilogue ----------------
  const float cN = rsqrtf(scal[0] * scal[1]);
  const float nF = (float)NROWS;
  float ks[8];
#pragma unroll
  for (int j = 0; j < 8; j++) ks[j] = scal[4 + l * 8 + j];
  float gf[8], btf[8];
  {
    float4 t0 = *(const float4*)&gamma[l*8]; float4 t1 = *(const float4*)&gamma[l*8+4];
    gf[0]=t0.x; gf[1]=t0.y; gf[2]=t0.z; gf[3]=t0.w;
    gf[4]=t1.x; gf[5]=t1.y; gf[6]=t1.z; gf[7]=t1.w;
    float4 u0 = *(const float4*)&beta[l*8];  float4 u1 = *(const float4*)&beta[l*8+4];
    btf[0]=u0.x; btf[1]=u0.y; btf[2]=u0.z; btf[3]=u0.w;
    btf[4]=u1.x; btf[5]=u1.y; btf[6]=u1.z; btf[7]=u1.w;
  }

#pragma unroll
  for (int i = 0; i < 8; i++) {
    const int r = m0 + w * 8 + i;
    const bool valid = r < NROWS;
    float q8[8], v8[8], p8[8];
    if (valid) {
      float4 t0 = *(const float4*)&Q[(size_t)r * CH + l * 8];
      float4 t1 = *(const float4*)&Q[(size_t)r * CH + l * 8 + 4];
      q8[0]=t0.x; q8[1]=t0.y; q8[2]=t0.z; q8[3]=t0.w;
      q8[4]=t1.x; q8[5]=t1.y; q8[6]=t1.z; q8[7]=t1.w;
      float4 v0 = *(const float4*)&V[(size_t)r * CH + l * 8];
      float4 v1 = *(const float4*)&V[(size_t)r * CH + l * 8 + 4];
      v8[0]=v0.x; v8[1]=v0.y; v8[2]=v0.z; v8[3]=v0.w;
      v8[4]=v1.x; v8[5]=v1.y; v8[6]=v1.z; v8[7]=v1.w;
      float4 p0 = *(const float4*)&P[(size_t)r * CH + l * 8];
      float4 p1 = *(const float4*)&P[(size_t)r * CH + l * 8 + 4];
      p8[0]=p0.x; p8[1]=p0.y; p8[2]=p0.z; p8[3]=p0.w;
      p8[4]=p1.x; p8[5]=p1.y; p8[6]=p1.z; p8[7]=p1.w;
    } else {
#pragma unroll
      for (int j = 0; j < 8; j++) { q8[j]=0.f; v8[j]=0.f; p8[j]=0.f; }
    }
    float dp = 0.f;
#pragma unroll
    for (int j = 0; j < 8; j++) dp = fmaf(q8[j], ks[j], dp);
    dp = wred(dp);
    const float denom = fmaf(cN, dp, nF);
    const float inv = 1.f / denom;

    float hm[8];
#pragma unroll
    for (int j = 0; j < 8; j++) {
      float attn = (fmaf(cN, acc[i][j], nF * v8[j])) * inv;
      hm[j] = 0.5f * (attn + p8[j]);
    }
    float s1 = 0.f, s2 = 0.f;
#pragma unroll
    for (int j = 0; j < 8; j++) { s1 += hm[j]; s2 = fmaf(hm[j], hm[j], s2); }
    s1 = wred(s1); s2 = wred(s2);
    const float mu = s1 * (1.f / CH);
    const float rs = rsqrtf(s2 * (1.f / CH) - mu * mu + 1e-5f);
    if (valid) {
      float o[8];
#pragma unroll
      for (int j = 0; j < 8; j++)
        o[j] = fmaxf((hm[j] - mu) * rs * gf[j] + btf[j], 0.f);
      float4 o0 = make_float4(o[0], o[1], o[2], o[3]);
      float4 o1 = make_float4(o[4], o[5], o[6], o[7]);
      *(float4*)&Cout[(size_t)r * CH + l * 8]     = o0;
      *(float4*)&Cout[(size_t)r * CH + l * 8 + 4] = o1;
    }
  }
}

// ---------------------------------------------------------------------------
extern "C" void kernel_launch(void* const* d_in, const int* in_sizes, int n_in,
                              void* d_out, int out_size) {
  (void)in_sizes; (void)n_in; (void)out_size;
  const float* x    = (const float*)d_in[0];
  const float* fc_w = (const float*)d_in[1];
  const float* fc_b = (const float*)d_in[2];
  const float* Wq_w = (const float*)d_in[3];
  const float* Wq_b = (const float*)d_in[4];
  const float* Wk_w = (const float*)d_in[5];
  const float* Wk_b = (const float*)d_in[6];
  const float* Wv_w = (const float*)d_in[7];
  const float* Wv_b = (const float*)d_in[8];
  const float* ln_g = (const float*)d_in[9];
  const float* ln_b = (const float*)d_in[10];
  float* out = (float*)d_out;

  float *hA, *hB, *q, *k, *v, *part, *kvs, *scal;
  cudaGetSymbolAddress((void**)&hA,   g_h);
  cudaGetSymbolAddress((void**)&hB,   g_h2);
  cudaGetSymbolAddress((void**)&q,    g_q);
  cudaGetSymbolAddress((void**)&k,    g_k);
  cudaGetSymbolAddress((void**)&v,    g_v);
  cudaGetSymbolAddress((void**)&part, g_part);
  cudaGetSymbolAddress((void**)&kvs,  g_kvs);
  cudaGetSymbolAddress((void**)&scal, g_scal);

  // h0 = relu(LN(x @ fc_w^T + fc_b))
  gemm_nt<true, false, false><<<MBLK, NTHR>>>(
      x, fc_w, fc_b, hA, ln_g, ln_b, nullptr, nullptr);

  for (int L = 0; L < 2; L++) {
    const float* h = L ? hB : hA;
    float* ob = L ? out : hB;
    const size_t wo = (size_t)L * CH * CH;
    const size_t bo = (size_t)L * CH;

    zero_kernel<<<1, CH + 4>>>(scal, CH + 4);
    gemm_nt<false, true, false><<<MBLK, NTHR>>>(
        h, Wq_w + wo, Wq_b + bo, q, nullptr, nullptr, scal + 0, nullptr);
    gemm_nt<false, true, true><<<MBLK, NTHR>>>(
        h, Wk_w + wo, Wk_b + bo, k, nullptr, nullptr, scal + 1, scal + 4);
    gemm_nt<false, false, false><<<MBLK, NTHR>>>(
        h, Wv_w + wo, Wv_b + bo, v, nullptr, nullptr, nullptr, nullptr);
    kvs_kernel<<<dim3(CH / BM, S_SLICES), NTHR>>>(k, v, part);
    kvs_reduce<<<64, 1024>>>(part, kvs);
    attn_kernel<<<MBLK, NTHR>>>(
        q, kvs, v, h, scal, ln_g + (size_t)(L + 1) * CH, ln_b + (size_t)(L + 1) * CH, ob);
  }
}